// round 7
// baseline (speedup 1.0000x reference)
#include <cuda_runtime.h>

// ---------------------------------------------------------------------------
// signalEncoding: B=256, S=512, SF=4, NSIG=50
// Kernel W (wcomp): compose per-signal fused conv weights ONCE -> g_W
// Kernel A (prep): x -> sharedCNN(sharedCNN(x)) + x -> LayerNorm -> g_D
// Kernel B (sig):  flat-balanced per-(bp,signal) fused stacks:
//   L12 = conv2(k5) o conv1(k7)  -> 4->4 k11 conv, then SELU
//   L34 = conv4(k5,d2) o conv3(k5) -> 4->1 k13 conv, then SELU
// Reflect boundaries exact via explicit H1/H3 edge values.
// Batch packed 2-wide into f32x2. All intermediates in SMEM.
// ---------------------------------------------------------------------------

#define NPOS 512
#define HALO 4
#define CST  528           // per-channel smem stride (float2), 528 % 16 == 0
#define NBP  128           // batch pairs
#define NSIG 50
#define NITEM (NBP * NSIG) // 6400
#define NCTA 740           // 5 CTAs/SM * 148 SMs = single wave
#define WSTRIDE 688        // packed per-signal weight block stride (floats)

// packed weight block offsets
#define OFF_W12  0    // 176: Weff12[o*44 + c*11 + t]
#define OFF_BE12 176  // 4
#define OFF_W2R  180  // 160: w2[o*40 + m*5 + j2]
#define OFF_B2R  340  // 4
#define OFF_W34  344  // 52: Weff34[c*13 + t]
#define OFF_BE34 396  // 1
#define OFF_W3R  397  // 40
#define OFF_B3R  437  // 2
#define OFF_W4R  439  // 10
#define OFF_B4R  449  // 1
#define OFF_W1R  450  // 224
#define OFF_B1R  674  // 8
#define WTOTAL   682

__device__ __forceinline__ int sidx(int c, int p) {
    int q = p + HALO;
    return c * CST + (q ^ ((q >> 4) & 3));
}

__device__ __forceinline__ int refl(int q) {
    q = q < 0 ? -q : q;
    return q > 511 ? 1022 - q : q;
}

union F2U { float2 f; unsigned long long u; };

__device__ __forceinline__ float2 ffma2(float2 a, float2 b, float2 c) {
    F2U ua, ub, uc, ud;
    ua.f = a; ub.f = b; uc.f = c;
    asm("fma.rn.f32x2 %0, %1, %2, %3;" : "=l"(ud.u) : "l"(ua.u), "l"(ub.u), "l"(uc.u));
    return ud.f;
}

__device__ __forceinline__ float2 splat(float w) { return make_float2(w, w); }

__device__ __forceinline__ float2 add2(float2 a, float2 b) {
    return make_float2(a.x + b.x, a.y + b.y);
}

__device__ __forceinline__ float selu_s(float x) {
    const float SC = 1.0507009873554805f;
    const float SA = 1.7580993408473766f;
    return x > 0.f ? SC * x : SA * expm1f(x);
}
__device__ __forceinline__ float2 selu2(float2 v) {
    return make_float2(selu_s(v.x), selu_s(v.y));
}

__device__ __forceinline__ void fill_halo(float2* buf, int C, int tid) {
    if (tid < C * 8) {
        int c = tid >> 3, k = tid & 7;
        if (k < 4) { int i = k + 1; buf[sidx(c, -i)]      = buf[sidx(c, i)]; }
        else       { int i = k - 3; buf[sidx(c, 511 + i)] = buf[sidx(c, 511 - i)]; }
    }
}

__device__ float2 g_D[NBP * 4 * NPOS];
__device__ float  g_W[NSIG * WSTRIDE];

// ---------------------------------------------------------------------------
// Kernel W: compose fused weights per signal (runs once, 50 blocks, trivial)
// ---------------------------------------------------------------------------

extern "C" __global__ void __launch_bounds__(128)
wcomp_kernel(const float* __restrict__ sw1, const float* __restrict__ sb1,
             const float* __restrict__ sw2, const float* __restrict__ sb2,
             const float* __restrict__ sw3, const float* __restrict__ sb3,
             const float* __restrict__ sw4, const float* __restrict__ sb4) {
    const int sig = blockIdx.x;
    float* w = g_W + sig * WSTRIDE;
    for (int i = threadIdx.x; i < WTOTAL; i += 128) {
        float v;
        if (i < 176) {
            // Weff12[o][c][t] = sum_m sum_j2 w2[o][m][j2] * w1[m][c][t-j2]
            int o = i / 44, rem = i % 44, c = rem / 11, t = rem % 11;
            const float* w2p = sw2 + sig * 160 + o * 40;
            const float* w1p = sw1 + sig * 224;
            float s = 0.f;
            #pragma unroll
            for (int m = 0; m < 8; m++)
                #pragma unroll
                for (int j2 = 0; j2 < 5; j2++) {
                    int j1 = t - j2;
                    if (j1 >= 0 && j1 <= 6)
                        s += w2p[m * 5 + j2] * w1p[m * 28 + c * 7 + j1];
                }
            v = s;
        } else if (i < 180) {
            int o = i - 176;
            float s = sb2[sig * 4 + o];
            #pragma unroll
            for (int m = 0; m < 8; m++) {
                float sm_ = 0.f;
                #pragma unroll
                for (int j2 = 0; j2 < 5; j2++) sm_ += sw2[sig * 160 + o * 40 + m * 5 + j2];
                s += sm_ * sb1[sig * 8 + m];
            }
            v = s;
        } else if (i < 340) {
            v = sw2[sig * 160 + (i - 180)];
        } else if (i < 344) {
            v = sb2[sig * 4 + (i - 340)];
        } else if (i < 396) {
            // Weff34[c][t] = sum_m sum_j4 w4[m][j4] * w3[m][c][t-2*j4]
            int k = i - 344, c = k / 13, t = k % 13;
            float s = 0.f;
            #pragma unroll
            for (int m = 0; m < 2; m++)
                #pragma unroll
                for (int j4 = 0; j4 < 5; j4++) {
                    int j3 = t - 2 * j4;
                    if (j3 >= 0 && j3 <= 4)
                        s += sw4[sig * 10 + m * 5 + j4] * sw3[sig * 40 + m * 20 + c * 5 + j3];
                }
            v = s;
        } else if (i == 396) {
            float s = sb4[sig];
            #pragma unroll
            for (int m = 0; m < 2; m++) {
                float sm_ = 0.f;
                #pragma unroll
                for (int j4 = 0; j4 < 5; j4++) sm_ += sw4[sig * 10 + m * 5 + j4];
                s += sm_ * sb3[sig * 2 + m];
            }
            v = s;
        } else if (i < 437) {
            v = sw3[sig * 40 + (i - 397)];
        } else if (i < 439) {
            v = sb3[sig * 2 + (i - 437)];
        } else if (i < 449) {
            v = sw4[sig * 10 + (i - 439)];
        } else if (i == 449) {
            v = sb4[sig];
        } else if (i < 674) {
            v = sw1[sig * 224 + (i - 450)];
        } else {
            v = sb1[sig * 8 + (i - 674)];
        }
        w[i] = v;
    }
}

// ---------------------------------------------------------------------------
// Kernel A: prep.  grid=128, block=512. (unchanged, validated)
// ---------------------------------------------------------------------------

__device__ __forceinline__ void shared_conv1(const float2* S, float2* Dst,
                                             const float* w1, const float* b1, int t) {
    #pragma unroll
    for (int o = 0; o < 8; o++) {
        float2 acc = splat(b1[o]);
        #pragma unroll
        for (int c = 0; c < 4; c++)
            #pragma unroll
            for (int j = 0; j < 5; j++) {
                float w = w1[o * 20 + c * 5 + j];
                acc = ffma2(splat(w), S[sidx(c, t - 2 + j)], acc);
            }
        Dst[sidx(o, t)] = selu2(acc);
    }
}

__device__ __forceinline__ void shared_conv2(const float2* S, const float* w2,
                                             const float* b2, int t, float2 out[4]) {
    #pragma unroll
    for (int o = 0; o < 4; o++) {
        float2 acc = splat(b2[o]);
        #pragma unroll
        for (int c = 0; c < 8; c++)
            #pragma unroll
            for (int j = 0; j < 5; j++) {
                float w = w2[o * 40 + c * 5 + j];
                acc = ffma2(splat(w), S[sidx(c, t - 4 + 2 * j)], acc);
            }
        out[o] = acc;
    }
}

extern "C" __global__ void __launch_bounds__(512)
prep_kernel(const float* __restrict__ lat,
            const float* __restrict__ sw1, const float* __restrict__ sb1,
            const float* __restrict__ sw2, const float* __restrict__ sb2,
            const float* __restrict__ lng, const float* __restrict__ lnb) {
    extern __shared__ unsigned char sm[];
    float2* X   = (float2*)sm;            // 4 * CST
    float2* A   = X + 4 * CST;            // 8 * CST
    float2* Bu  = A + 8 * CST;            // 4 * CST
    float*  W   = (float*)(Bu + 4 * CST); // 336 floats
    float2* RED = (float2*)(W + 336);     // 64 float2

    const int t  = threadIdx.x;
    const int bp = blockIdx.x;
    const int lane = t & 31, wid = t >> 5;

    if (t < 332) {
        float v;
        if      (t < 160) v = sw1[t];
        else if (t < 168) v = sb1[t - 160];
        else if (t < 328) v = sw2[t - 168];
        else              v = sb2[t - 328];
        W[t] = v;
    }
    const float* w1 = W, * b1 = W + 160, * w2 = W + 168, * b2 = W + 328;

    float4 v0 = reinterpret_cast<const float4*>(lat + (size_t)(2 * bp)     * 2048)[t];
    float4 v1 = reinterpret_cast<const float4*>(lat + (size_t)(2 * bp + 1) * 2048)[t];
    X[sidx(0, t)] = make_float2(v0.x, v1.x);
    X[sidx(1, t)] = make_float2(v0.y, v1.y);
    X[sidx(2, t)] = make_float2(v0.z, v1.z);
    X[sidx(3, t)] = make_float2(v0.w, v1.w);
    __syncthreads();
    fill_halo(X, 4, t);
    __syncthreads();

    shared_conv1(X, A, w1, b1, t);
    __syncthreads(); fill_halo(A, 8, t); __syncthreads();
    {
        float2 tmp[4];
        shared_conv2(A, w2, b2, t, tmp);
        __syncthreads();
        #pragma unroll
        for (int c = 0; c < 4; c++) Bu[sidx(c, t)] = tmp[c];
    }
    __syncthreads(); fill_halo(Bu, 4, t); __syncthreads();

    shared_conv1(Bu, A, w1, b1, t);
    __syncthreads(); fill_halo(A, 8, t); __syncthreads();
    float2 dv[4];
    {
        float2 cc[4];
        shared_conv2(A, w2, b2, t, cc);
        #pragma unroll
        for (int c = 0; c < 4; c++) dv[c] = add2(cc[c], X[sidx(c, t)]);
    }

    float2 mean[4], var[4];
    {
        float2 sv[4];
        #pragma unroll
        for (int c = 0; c < 4; c++) sv[c] = dv[c];
        #pragma unroll
        for (int c = 0; c < 4; c++)
            for (int off = 16; off; off >>= 1) {
                sv[c].x += __shfl_xor_sync(0xffffffffu, sv[c].x, off);
                sv[c].y += __shfl_xor_sync(0xffffffffu, sv[c].y, off);
            }
        if (lane == 0)
            #pragma unroll
            for (int c = 0; c < 4; c++) RED[c * 16 + wid] = sv[c];
        __syncthreads();
        if (t < 32) {
            #pragma unroll
            for (int c = 0; c < 4; c++) {
                float2 v = (lane < 16) ? RED[c * 16 + lane] : make_float2(0.f, 0.f);
                for (int off = 8; off; off >>= 1) {
                    v.x += __shfl_xor_sync(0xffffffffu, v.x, off);
                    v.y += __shfl_xor_sync(0xffffffffu, v.y, off);
                }
                if (lane == 0) RED[c * 16] = v;
            }
        }
        __syncthreads();
        const float inv = 1.0f / 512.0f;
        #pragma unroll
        for (int c = 0; c < 4; c++) {
            float2 s = RED[c * 16];
            mean[c] = make_float2(s.x * inv, s.y * inv);
        }
        __syncthreads();
    }
    {
        float2 sv[4];
        #pragma unroll
        for (int c = 0; c < 4; c++) {
            float dx = dv[c].x - mean[c].x, dy = dv[c].y - mean[c].y;
            sv[c] = make_float2(dx * dx, dy * dy);
        }
        #pragma unroll
        for (int c = 0; c < 4; c++)
            for (int off = 16; off; off >>= 1) {
                sv[c].x += __shfl_xor_sync(0xffffffffu, sv[c].x, off);
                sv[c].y += __shfl_xor_sync(0xffffffffu, sv[c].y, off);
            }
        if (lane == 0)
            #pragma unroll
            for (int c = 0; c < 4; c++) RED[c * 16 + wid] = sv[c];
        __syncthreads();
        if (t < 32) {
            #pragma unroll
            for (int c = 0; c < 4; c++) {
                float2 v = (lane < 16) ? RED[c * 16 + lane] : make_float2(0.f, 0.f);
                for (int off = 8; off; off >>= 1) {
                    v.x += __shfl_xor_sync(0xffffffffu, v.x, off);
                    v.y += __shfl_xor_sync(0xffffffffu, v.y, off);
                }
                if (lane == 0) RED[c * 16] = v;
            }
        }
        __syncthreads();
        const float inv = 1.0f / 512.0f;
        #pragma unroll
        for (int c = 0; c < 4; c++) {
            float2 s = RED[c * 16];
            var[c] = make_float2(s.x * inv, s.y * inv);
        }
    }

    const float EPS = 1e-10f;
    float g = lng[t], bb = lnb[t];
    #pragma unroll
    for (int c = 0; c < 4; c++) {
        float rx = 1.0f / sqrtf(var[c].x + EPS);
        float ry = 1.0f / sqrtf(var[c].y + EPS);
        float2 dn;
        dn.x = (dv[c].x - mean[c].x) * rx * g + bb;
        dn.y = (dv[c].y - mean[c].y) * ry * g + bb;
        g_D[(size_t)(bp * 4 + c) * NPOS + t] = dn;
    }
}

// ---------------------------------------------------------------------------
// Kernel B: flat-balanced fused stacks. grid=NCTA(740), block=128.
// Each CTA claims a contiguous slice of the 6400 (bp, sig) items.
// ---------------------------------------------------------------------------

extern "C" __global__ void __launch_bounds__(128, 5)
sig_kernel(float* __restrict__ out) {
    extern __shared__ unsigned char sm[];
    float2* D   = (float2*)sm;            // 4 * CST
    float2* H2  = D + 4 * CST;            // 4 * CST
    float2* He  = H2 + 4 * CST;           // 64: H1 edges [m*8+k], k<4: q=k else q=508+(k-4)
    float2* H3e = He + 64;                // 32: H3 edges [m*16+k], k<8: q=k else q=504+(k-8)
    float*  W   = (float*)(H3e + 32);     // WTOTAL floats

    const int tid  = threadIdx.x;
    const int base = tid * 4;

    const int kcta  = blockIdx.x;
    const int start = (int)(((long long)kcta * NITEM) / NCTA);
    const int end   = (int)(((long long)(kcta + 1) * NITEM) / NCTA);

    int cur_bp = -1;

    for (int it = start; it < end; ++it) {
        const int bp  = it / NSIG;
        const int sig = it - bp * NSIG;

        if (bp != cur_bp) {
            __syncthreads();   // prior item's D/H2/W reads complete
            const float2* gd = g_D + (size_t)bp * 4 * NPOS;
            for (int i = tid; i < 4 * NPOS; i += 128) {
                int c = i >> 9, p = i & 511;
                D[sidx(c, p)] = gd[i];
            }
            __syncthreads();
            fill_halo(D, 4, tid);
            cur_bp = bp;
            __syncthreads();
        } else {
            __syncthreads();   // protect W / H2 overwrite
        }

        const float* gw = g_W + sig * WSTRIDE;

        // stage: tids 64..127 copy packed weights; tids 0..63 compute H1 edges
        if (tid >= 64) {
            for (int i = tid - 64; i < WTOTAL; i += 64) W[i] = gw[i];
        } else {
            int m = tid >> 3, kk = tid & 7;
            int q = kk < 4 ? kk : 508 + (kk - 4);
            float2 a = splat(gw[OFF_B1R + m]);
            const float* w1p = gw + OFF_W1R + m * 28;
            #pragma unroll
            for (int c = 0; c < 4; c++)
                #pragma unroll
                for (int j1 = 0; j1 < 7; j1++)
                    a = ffma2(splat(w1p[c * 7 + j1]), D[sidx(c, q - 3 + j1)], a);
            He[tid] = a;
        }
        __syncthreads();

        const float* W12 = W + OFF_W12, * BE12 = W + OFF_BE12;
        const float* W2R = W + OFF_W2R, * B2R  = W + OFF_B2R;
        const float* W34 = W + OFF_W34;
        const float* W4R = W + OFF_W4R;

        // ---- fused L12: 4->4 k11 composed conv + SELU -> H2 ----
        if (tid != 0 && tid != 127) {
            float2 acc[4][4];
            #pragma unroll
            for (int o = 0; o < 4; o++) {
                float2 b = splat(BE12[o]);
                #pragma unroll
                for (int r = 0; r < 4; r++) acc[o][r] = b;
            }
            #pragma unroll
            for (int c = 0; c < 4; c++) {
                float2 in[14];
                #pragma unroll
                for (int t = 0; t < 14; t++) in[t] = D[sidx(c, base - 5 + t)];
                #pragma unroll
                for (int o = 0; o < 4; o++)
                    #pragma unroll
                    for (int t = 0; t < 11; t++) {
                        float2 wv = splat(W12[o * 44 + c * 11 + t]);
                        #pragma unroll
                        for (int r = 0; r < 4; r++)
                            acc[o][r] = ffma2(wv, in[r + t], acc[o][r]);
                    }
            }
            #pragma unroll
            for (int o = 0; o < 4; o++)
                #pragma unroll
                for (int r = 0; r < 4; r++)
                    H2[sidx(o, base + r)] = selu2(acc[o][r]);
        } else {
            const int left = (tid == 0);
            #pragma unroll
            for (int e = 0; e < 2; e++) {
                int p = left ? e : 510 + e;
                #pragma unroll
                for (int o = 0; o < 4; o++) {
                    float2 a = splat(B2R[o]);
                    #pragma unroll
                    for (int m = 0; m < 8; m++)
                        #pragma unroll
                        for (int j2 = 0; j2 < 5; j2++) {
                            int q = refl(p - 2 + j2);
                            int k = q < 8 ? q : q - 504;
                            a = ffma2(splat(W2R[o * 40 + m * 5 + j2]), He[m * 8 + k], a);
                        }
                    H2[sidx(o, p)] = selu2(a);
                }
            }
            #pragma unroll
            for (int e = 0; e < 2; e++) {
                int p = left ? 2 + e : 508 + e;
                float2 a[4];
                #pragma unroll
                for (int o = 0; o < 4; o++) a[o] = splat(BE12[o]);
                #pragma unroll
                for (int c = 0; c < 4; c++)
                    #pragma unroll
                    for (int t = 0; t < 11; t++) {
                        float2 dv = D[sidx(c, p - 5 + t)];
                        #pragma unroll
                        for (int o = 0; o < 4; o++)
                            a[o] = ffma2(splat(W12[o * 44 + c * 11 + t]), dv, a[o]);
                    }
                #pragma unroll
                for (int o = 0; o < 4; o++) H2[sidx(o, p)] = selu2(a[o]);
            }
        }
        __syncthreads();
        fill_halo(H2, 4, tid);
        __syncthreads();

        // ---- H3 edge values ----
        if (tid < 32) {
            int m = tid >> 4, kk = tid & 15;
            int q = kk < 8 ? kk : 504 + (kk - 8);
            float2 a = splat(W[OFF_B3R + m]);
            #pragma unroll
            for (int c = 0; c < 4; c++)
                #pragma unroll
                for (int j3 = 0; j3 < 5; j3++)
                    a = ffma2(splat(W[OFF_W3R + m * 20 + c * 5 + j3]), H2[sidx(c, q - 2 + j3)], a);
            H3e[m * 16 + kk] = a;
        }
        __syncthreads();

        // ---- fused L34: 4->1 k13 composed conv + SELU -> out ----
        float2 res[4];
        if (tid != 0 && tid != 127) {
            float2 acc[4];
            const float be34 = W[OFF_BE34];
            #pragma unroll
            for (int r = 0; r < 4; r++) acc[r] = splat(be34);
            #pragma unroll
            for (int c = 0; c < 4; c++) {
                float2 in[16];
                #pragma unroll
                for (int t = 0; t < 16; t++) in[t] = H2[sidx(c, base - 6 + t)];
                #pragma unroll
                for (int t = 0; t < 13; t++) {
                    float2 wv = splat(W34[c * 13 + t]);
                    #pragma unroll
                    for (int r = 0; r < 4; r++)
                        acc[r] = ffma2(wv, in[r + t], acc[r]);
                }
            }
            #pragma unroll
            for (int r = 0; r < 4; r++) res[r] = selu2(acc[r]);
        } else {
            const float b4 = W[OFF_B4R];
            #pragma unroll
            for (int r = 0; r < 4; r++) {
                int p = base + r;
                float2 a = splat(b4);
                #pragma unroll
                for (int m = 0; m < 2; m++)
                    #pragma unroll
                    for (int j4 = 0; j4 < 5; j4++) {
                        int q = refl(p - 4 + 2 * j4);
                        int k = q < 8 ? q : 8 + (q - 504);
                        a = ffma2(splat(W4R[m * 5 + j4]), H3e[m * 16 + k], a);
                    }
                res[r] = selu2(a);
            }
        }

        const size_t o0 = ((size_t)(2 * bp)     * 50 + sig) * NPOS + base;
        const size_t o1 = ((size_t)(2 * bp + 1) * 50 + sig) * NPOS + base;
        *reinterpret_cast<float4*>(out + o0) =
            make_float4(res[0].x, res[1].x, res[2].x, res[3].x);
        *reinterpret_cast<float4*>(out + o1) =
            make_float4(res[0].y, res[1].y, res[2].y, res[3].y);
    }
}

// ---------------------------------------------------------------------------
// launch
// ---------------------------------------------------------------------------

static const int SMEM_PREP = (16 * CST) * (int)sizeof(float2) + 336 * 4 + 64 * (int)sizeof(float2);
static const int SMEM_SIG  = (8 * CST + 96) * (int)sizeof(float2) + WSTRIDE * 4;

extern "C" void kernel_launch(void* const* d_in, const int* in_sizes, int n_in,
                              void* d_out, int out_size) {
    const float* lat  = (const float*)d_in[0];
    const float* shw1 = (const float*)d_in[1];
    const float* shb1 = (const float*)d_in[2];
    const float* shw2 = (const float*)d_in[3];
    const float* shb2 = (const float*)d_in[4];
    const float* lng  = (const float*)d_in[5];
    const float* lnb  = (const float*)d_in[6];
    const float* sgw1 = (const float*)d_in[7];
    const float* sgb1 = (const float*)d_in[8];
    const float* sgw2 = (const float*)d_in[9];
    const float* sgb2 = (const float*)d_in[10];
    const float* sgw3 = (const float*)d_in[11];
    const float* sgb3 = (const float*)d_in[12];
    const float* sgw4 = (const float*)d_in[13];
    const float* sgb4 = (const float*)d_in[14];
    float* out = (float*)d_out;

    cudaFuncSetAttribute(prep_kernel, cudaFuncAttributeMaxDynamicSharedMemorySize, SMEM_PREP);
    cudaFuncSetAttribute(sig_kernel,  cudaFuncAttributeMaxDynamicSharedMemorySize, SMEM_SIG);

    wcomp_kernel<<<NSIG, 128>>>(sgw1, sgb1, sgw2, sgb2, sgw3, sgb3, sgw4, sgb4);
    prep_kernel<<<NBP, 512, SMEM_PREP>>>(lat, shw1, shb1, shw2, shb2, lng, lnb);
    sig_kernel<<<NCTA, 128, SMEM_SIG>>>(out);
}

// round 8
// speedup vs baseline: 1.1566x; 1.1566x over previous
#include <cuda_runtime.h>

// ---------------------------------------------------------------------------
// signalEncoding: B=256, S=512, SF=4, NSIG=50
// wcomp : compose per-signal weights once -> g_W (pre-splatted float2 blocks)
// prep  : x -> sharedCNN(sharedCNN(x)) + x -> LayerNorm -> g_D
// sig   : 512 thr = 1 position/thread, no swizzle, lane-stride-1 smem.
//         L12 = conv2 o conv1 fused (4->4 k11 composed) + SELU
//         L3, L4 explicit (uniform path for all threads; halo +-4 suffices)
// ---------------------------------------------------------------------------

#define NPOS 512
#define HALO 4
#define CST  528
#define NBP  128
#define NSIG 50
#define NITEM (NBP * NSIG)   // 6400
#define NCTA  296            // 2 CTAs/SM * 148 SMs = one wave
#define WSTRIDE 944          // floats per signal block (16B-aligned multiple)
#define WTOTAL  942

// float2-index offsets into the packed block (splatted sections)
#define F2_W12S  0    // [o*48 + c*12 + t], t<11 real, t=11 zero   (192 f2)
#define F2_BE12S 192  // [o]                                        (4 f2)
#define F2_W3RS  196  // [m*32 + c*8 + j], j<5 real, j>=5 zero      (64 f2)
#define F2_B3RS  260  // [m]                                        (2 f2)
#define F2_W4RS  262  // [m*5 + j]                                  (10 f2)
#define F2_B4RS  272  // [0]                                        (1 f2)
// raw float offsets (edge path + He)
#define OFF_W2R  546  // 160
#define OFF_B2R  706  // 4
#define OFF_W1R  710  // 224
#define OFF_B1R  934  // 8

__device__ __forceinline__ int idx(int c, int p) { return c * CST + p + HALO; }

// prep kernel keeps the old swizzled layout (validated)
__device__ __forceinline__ int sidx(int c, int p) {
    int q = p + HALO;
    return c * CST + (q ^ ((q >> 4) & 3));
}

__device__ __forceinline__ int refl(int q) {
    q = q < 0 ? -q : q;
    return q > 511 ? 1022 - q : q;
}

union F2U { float2 f; unsigned long long u; };

__device__ __forceinline__ float2 ffma2(float2 a, float2 b, float2 c) {
    F2U ua, ub, uc, ud;
    ua.f = a; ub.f = b; uc.f = c;
    asm("fma.rn.f32x2 %0, %1, %2, %3;" : "=l"(ud.u) : "l"(ua.u), "l"(ub.u), "l"(uc.u));
    return ud.f;
}

__device__ __forceinline__ float2 splat(float w) { return make_float2(w, w); }

__device__ __forceinline__ float2 add2(float2 a, float2 b) {
    return make_float2(a.x + b.x, a.y + b.y);
}

__device__ __forceinline__ float selu_s(float x) {
    const float SC = 1.0507009873554805f;
    const float SA = 1.7580993408473766f;
    return x > 0.f ? SC * x : SA * expm1f(x);
}
__device__ __forceinline__ float2 selu2(float2 v) {
    return make_float2(selu_s(v.x), selu_s(v.y));
}

__device__ __forceinline__ void fill_halo_sw(float2* buf, int C, int tid) {
    if (tid < C * 8) {
        int c = tid >> 3, k = tid & 7;
        if (k < 4) { int i = k + 1; buf[sidx(c, -i)]      = buf[sidx(c, i)]; }
        else       { int i = k - 3; buf[sidx(c, 511 + i)] = buf[sidx(c, 511 - i)]; }
    }
}

__device__ float2 g_D[NBP * 4 * NPOS];
__device__ float  g_W[NSIG * WSTRIDE];

// ---------------------------------------------------------------------------
// wcomp: build packed per-signal weight blocks (splatted float2 sections)
// ---------------------------------------------------------------------------

extern "C" __global__ void __launch_bounds__(128)
wcomp_kernel(const float* __restrict__ sw1, const float* __restrict__ sb1,
             const float* __restrict__ sw2, const float* __restrict__ sb2,
             const float* __restrict__ sw3, const float* __restrict__ sb3,
             const float* __restrict__ sw4, const float* __restrict__ sb4) {
    const int sig = blockIdx.x;
    float* w = g_W + sig * WSTRIDE;
    for (int i = threadIdx.x; i < WTOTAL; i += 128) {
        float v;
        if (i < 384) {                       // W12s splat
            int k = i >> 1, o = k / 48, r = k % 48, c = r / 12, t = r % 12;
            if (t == 11) v = 0.f;
            else {
                float s = 0.f;
                const float* w2p = sw2 + sig * 160 + o * 40;
                const float* w1p = sw1 + sig * 224;
                #pragma unroll
                for (int m = 0; m < 8; m++)
                    #pragma unroll
                    for (int j2 = 0; j2 < 5; j2++) {
                        int j1 = t - j2;
                        if (j1 >= 0 && j1 <= 6)
                            s += w2p[m * 5 + j2] * w1p[m * 28 + c * 7 + j1];
                    }
                v = s;
            }
        } else if (i < 392) {                // BE12s splat
            int o = (i - 384) >> 1;
            float s = sb2[sig * 4 + o];
            #pragma unroll
            for (int m = 0; m < 8; m++) {
                float sm_ = 0.f;
                #pragma unroll
                for (int j2 = 0; j2 < 5; j2++) sm_ += sw2[sig * 160 + o * 40 + m * 5 + j2];
                s += sm_ * sb1[sig * 8 + m];
            }
            v = s;
        } else if (i < 520) {                // W3Rs splat (j padded to 8)
            int k = (i - 392) >> 1, m = k / 32, r = k % 32, c = r / 8, j = r % 8;
            v = (j < 5) ? sw3[sig * 40 + m * 20 + c * 5 + j] : 0.f;
        } else if (i < 524) {                // B3Rs splat
            v = sb3[sig * 2 + ((i - 520) >> 1)];
        } else if (i < 544) {                // W4Rs splat
            int k = (i - 524) >> 1;
            v = sw4[sig * 10 + k];
        } else if (i < 546) {                // B4Rs splat
            v = sb4[sig];
        } else if (i < 706) {
            v = sw2[sig * 160 + (i - OFF_W2R)];
        } else if (i < 710) {
            v = sb2[sig * 4 + (i - OFF_B2R)];
        } else if (i < 934) {
            v = sw1[sig * 224 + (i - OFF_W1R)];
        } else {
            v = sb1[sig * 8 + (i - OFF_B1R)];
        }
        w[i] = v;
    }
}

// ---------------------------------------------------------------------------
// prep (unchanged, validated)
// ---------------------------------------------------------------------------

__device__ __forceinline__ void shared_conv1(const float2* S, float2* Dst,
                                             const float* w1, const float* b1, int t) {
    #pragma unroll
    for (int o = 0; o < 8; o++) {
        float2 acc = splat(b1[o]);
        #pragma unroll
        for (int c = 0; c < 4; c++)
            #pragma unroll
            for (int j = 0; j < 5; j++) {
                float w = w1[o * 20 + c * 5 + j];
                acc = ffma2(splat(w), S[sidx(c, t - 2 + j)], acc);
            }
        Dst[sidx(o, t)] = selu2(acc);
    }
}

__device__ __forceinline__ void shared_conv2(const float2* S, const float* w2,
                                             const float* b2, int t, float2 out[4]) {
    #pragma unroll
    for (int o = 0; o < 4; o++) {
        float2 acc = splat(b2[o]);
        #pragma unroll
        for (int c = 0; c < 8; c++)
            #pragma unroll
            for (int j = 0; j < 5; j++) {
                float w = w2[o * 40 + c * 5 + j];
                acc = ffma2(splat(w), S[sidx(c, t - 4 + 2 * j)], acc);
            }
        out[o] = acc;
    }
}

extern "C" __global__ void __launch_bounds__(512)
prep_kernel(const float* __restrict__ lat,
            const float* __restrict__ sw1, const float* __restrict__ sb1,
            const float* __restrict__ sw2, const float* __restrict__ sb2,
            const float* __restrict__ lng, const float* __restrict__ lnb) {
    extern __shared__ unsigned char sm[];
    float2* X   = (float2*)sm;
    float2* A   = X + 4 * CST;
    float2* Bu  = A + 8 * CST;
    float*  W   = (float*)(Bu + 4 * CST);
    float2* RED = (float2*)(W + 336);

    const int t  = threadIdx.x;
    const int bp = blockIdx.x;
    const int lane = t & 31, wid = t >> 5;

    if (t < 332) {
        float v;
        if      (t < 160) v = sw1[t];
        else if (t < 168) v = sb1[t - 160];
        else if (t < 328) v = sw2[t - 168];
        else              v = sb2[t - 328];
        W[t] = v;
    }
    const float* w1 = W, * b1 = W + 160, * w2 = W + 168, * b2 = W + 328;

    float4 v0 = reinterpret_cast<const float4*>(lat + (size_t)(2 * bp)     * 2048)[t];
    float4 v1 = reinterpret_cast<const float4*>(lat + (size_t)(2 * bp + 1) * 2048)[t];
    X[sidx(0, t)] = make_float2(v0.x, v1.x);
    X[sidx(1, t)] = make_float2(v0.y, v1.y);
    X[sidx(2, t)] = make_float2(v0.z, v1.z);
    X[sidx(3, t)] = make_float2(v0.w, v1.w);
    __syncthreads();
    fill_halo_sw(X, 4, t);
    __syncthreads();

    shared_conv1(X, A, w1, b1, t);
    __syncthreads(); fill_halo_sw(A, 8, t); __syncthreads();
    {
        float2 tmp[4];
        shared_conv2(A, w2, b2, t, tmp);
        __syncthreads();
        #pragma unroll
        for (int c = 0; c < 4; c++) Bu[sidx(c, t)] = tmp[c];
    }
    __syncthreads(); fill_halo_sw(Bu, 4, t); __syncthreads();

    shared_conv1(Bu, A, w1, b1, t);
    __syncthreads(); fill_halo_sw(A, 8, t); __syncthreads();
    float2 dv[4];
    {
        float2 cc[4];
        shared_conv2(A, w2, b2, t, cc);
        #pragma unroll
        for (int c = 0; c < 4; c++) dv[c] = add2(cc[c], X[sidx(c, t)]);
    }

    float2 mean[4], var[4];
    {
        float2 sv[4];
        #pragma unroll
        for (int c = 0; c < 4; c++) sv[c] = dv[c];
        #pragma unroll
        for (int c = 0; c < 4; c++)
            for (int off = 16; off; off >>= 1) {
                sv[c].x += __shfl_xor_sync(0xffffffffu, sv[c].x, off);
                sv[c].y += __shfl_xor_sync(0xffffffffu, sv[c].y, off);
            }
        if (lane == 0)
            #pragma unroll
            for (int c = 0; c < 4; c++) RED[c * 16 + wid] = sv[c];
        __syncthreads();
        if (t < 32) {
            #pragma unroll
            for (int c = 0; c < 4; c++) {
                float2 v = (lane < 16) ? RED[c * 16 + lane] : make_float2(0.f, 0.f);
                for (int off = 8; off; off >>= 1) {
                    v.x += __shfl_xor_sync(0xffffffffu, v.x, off);
                    v.y += __shfl_xor_sync(0xffffffffu, v.y, off);
                }
                if (lane == 0) RED[c * 16] = v;
            }
        }
        __syncthreads();
        const float inv = 1.0f / 512.0f;
        #pragma unroll
        for (int c = 0; c < 4; c++) {
            float2 s = RED[c * 16];
            mean[c] = make_float2(s.x * inv, s.y * inv);
        }
        __syncthreads();
    }
    {
        float2 sv[4];
        #pragma unroll
        for (int c = 0; c < 4; c++) {
            float dx = dv[c].x - mean[c].x, dy = dv[c].y - mean[c].y;
            sv[c] = make_float2(dx * dx, dy * dy);
        }
        #pragma unroll
        for (int c = 0; c < 4; c++)
            for (int off = 16; off; off >>= 1) {
                sv[c].x += __shfl_xor_sync(0xffffffffu, sv[c].x, off);
                sv[c].y += __shfl_xor_sync(0xffffffffu, sv[c].y, off);
            }
        if (lane == 0)
            #pragma unroll
            for (int c = 0; c < 4; c++) RED[c * 16 + wid] = sv[c];
        __syncthreads();
        if (t < 32) {
            #pragma unroll
            for (int c = 0; c < 4; c++) {
                float2 v = (lane < 16) ? RED[c * 16 + lane] : make_float2(0.f, 0.f);
                for (int off = 8; off; off >>= 1) {
                    v.x += __shfl_xor_sync(0xffffffffu, v.x, off);
                    v.y += __shfl_xor_sync(0xffffffffu, v.y, off);
                }
                if (lane == 0) RED[c * 16] = v;
            }
        }
        __syncthreads();
        const float inv = 1.0f / 512.0f;
        #pragma unroll
        for (int c = 0; c < 4; c++) {
            float2 s = RED[c * 16];
            var[c] = make_float2(s.x * inv, s.y * inv);
        }
    }

    const float EPS = 1e-10f;
    float g = lng[t], bb = lnb[t];
    #pragma unroll
    for (int c = 0; c < 4; c++) {
        float rx = 1.0f / sqrtf(var[c].x + EPS);
        float ry = 1.0f / sqrtf(var[c].y + EPS);
        float2 dn;
        dn.x = (dv[c].x - mean[c].x) * rx * g + bb;
        dn.y = (dv[c].y - mean[c].y) * ry * g + bb;
        g_D[(size_t)(bp * 4 + c) * NPOS + t] = dn;
    }
}

// ---------------------------------------------------------------------------
// sig: 512 threads, one position per thread. grid = NCTA.
// ---------------------------------------------------------------------------

extern "C" __global__ void __launch_bounds__(512, 2)
sig_kernel(float* __restrict__ out) {
    extern __shared__ unsigned char sm[];
    float*  W  = (float*)sm;                       // WSTRIDE floats (16B aligned)
    float2* D  = (float2*)sm + (WSTRIDE / 2);      // 4 * CST
    float2* H2 = D + 4 * CST;                      // 4 * CST
    float2* H3 = H2 + 4 * CST;                     // 2 * CST
    float2* He = H3 + 2 * CST;                     // 64

    const int p = threadIdx.x;           // position 0..511
    const int kcta  = blockIdx.x;
    const int start = (int)(((long long)kcta * NITEM) / NCTA);
    const int end   = (int)(((long long)(kcta + 1) * NITEM) / NCTA);

    int cur_bp = -1;

    for (int it = start; it < end; ++it) {
        const int bp  = it / NSIG;
        const int sig = it - bp * NSIG;

        __syncthreads();   // prior item's reads of W/He/H2/H3 (and D) complete

        if (bp != cur_bp) {
            const float2* gd = g_D + (size_t)bp * 4 * NPOS;
            for (int i = p; i < 4 * NPOS; i += 512) {
                int c = i >> 9, pp = i & 511;
                float2 v = gd[i];
                D[idx(c, pp)] = v;
                if (pp >= 1 && pp <= 4)     D[idx(c, -pp)]       = v;
                if (pp >= 507 && pp <= 510) D[idx(c, 1022 - pp)] = v;
            }
            cur_bp = bp;
            __syncthreads();
        }

        const float* gw = g_W + sig * WSTRIDE;

        // stage: tids >=64 copy weight block; tids 0..63 compute H1 edge values
        if (p >= 64) {
            for (int i = p - 64; i < WTOTAL; i += 448) W[i] = gw[i];
        } else {
            int m = p >> 3, kk = p & 7;
            int q = kk < 4 ? kk : 508 + (kk - 4);
            float2 a = splat(gw[OFF_B1R + m]);
            const float* w1p = gw + OFF_W1R + m * 28;
            #pragma unroll
            for (int c = 0; c < 4; c++)
                #pragma unroll
                for (int j1 = 0; j1 < 7; j1++)
                    a = ffma2(splat(w1p[c * 7 + j1]), D[idx(c, q - 3 + j1)], a);
            He[p] = a;
        }
        __syncthreads();

        const float2* Wf2 = (const float2*)W;

        // ---- L12: composed 4->4 k11 + SELU -> H2 (with inline halo mirror) ----
        {
            float2 acc[4];
            if (p >= 2 && p < 510) {
                #pragma unroll
                for (int o = 0; o < 4; o++) acc[o] = Wf2[F2_BE12S + o];
                #pragma unroll
                for (int c = 0; c < 4; c++) {
                    float2 d[11];
                    #pragma unroll
                    for (int t = 0; t < 11; t++) d[t] = D[idx(c, p - 5 + t)];
                    #pragma unroll
                    for (int o = 0; o < 4; o++) {
                        const float2* ws = Wf2 + F2_W12S + o * 48 + c * 12;
                        const float4* wq4 = (const float4*)ws;
                        #pragma unroll
                        for (int tt = 0; tt < 5; tt++) {
                            float4 wq = wq4[tt];
                            acc[o] = ffma2(make_float2(wq.x, wq.y), d[2 * tt],     acc[o]);
                            acc[o] = ffma2(make_float2(wq.z, wq.w), d[2 * tt + 1], acc[o]);
                        }
                        acc[o] = ffma2(ws[10], d[10], acc[o]);
                    }
                }
            } else {
                // exact edge path via explicit H1 edge values + raw conv2 weights
                #pragma unroll
                for (int o = 0; o < 4; o++) {
                    float2 a = splat(W[OFF_B2R + o]);
                    #pragma unroll
                    for (int m = 0; m < 8; m++)
                        #pragma unroll
                        for (int j2 = 0; j2 < 5; j2++) {
                            int q = refl(p - 2 + j2);
                            int k = q < 8 ? q : q - 504;
                            a = ffma2(splat(W[OFF_W2R + o * 40 + m * 5 + j2]),
                                      He[m * 8 + k], a);
                        }
                    acc[o] = a;
                }
            }
            #pragma unroll
            for (int o = 0; o < 4; o++) {
                float2 v = selu2(acc[o]);
                H2[idx(o, p)] = v;
                if (p >= 1 && p <= 4)     H2[idx(o, -p)]       = v;
                if (p >= 507 && p <= 510) H2[idx(o, 1022 - p)] = v;
            }
        }
        __syncthreads();

        // ---- L3: 4->2 k5 (linear) -> H3 (uniform for all p; halo +-4 covers) ----
        {
            float2 a0 = Wf2[F2_B3RS + 0];
            float2 a1 = Wf2[F2_B3RS + 1];
            #pragma unroll
            for (int c = 0; c < 4; c++) {
                float2 h[5];
                #pragma unroll
                for (int j = 0; j < 5; j++) h[j] = H2[idx(c, p - 2 + j)];
                {
                    const float2* ws = Wf2 + F2_W3RS + 0 * 32 + c * 8;
                    const float4* wq4 = (const float4*)ws;
                    float4 wa = wq4[0], wb = wq4[1];
                    a0 = ffma2(make_float2(wa.x, wa.y), h[0], a0);
                    a0 = ffma2(make_float2(wa.z, wa.w), h[1], a0);
                    a0 = ffma2(make_float2(wb.x, wb.y), h[2], a0);
                    a0 = ffma2(make_float2(wb.z, wb.w), h[3], a0);
                    a0 = ffma2(ws[4], h[4], a0);
                }
                {
                    const float2* ws = Wf2 + F2_W3RS + 1 * 32 + c * 8;
                    const float4* wq4 = (const float4*)ws;
                    float4 wa = wq4[0], wb = wq4[1];
                    a1 = ffma2(make_float2(wa.x, wa.y), h[0], a1);
                    a1 = ffma2(make_float2(wa.z, wa.w), h[1], a1);
                    a1 = ffma2(make_float2(wb.x, wb.y), h[2], a1);
                    a1 = ffma2(make_float2(wb.z, wb.w), h[3], a1);
                    a1 = ffma2(ws[4], h[4], a1);
                }
            }
            H3[idx(0, p)] = a0;
            H3[idx(1, p)] = a1;
            if (p >= 1 && p <= 4) {
                H3[idx(0, -p)] = a0; H3[idx(1, -p)] = a1;
            }
            if (p >= 507 && p <= 510) {
                H3[idx(0, 1022 - p)] = a0; H3[idx(1, 1022 - p)] = a1;
            }
        }
        __syncthreads();

        // ---- L4: 2->1 k5 d2 + SELU -> out (uniform; dilated taps within +-4) ----
        {
            float2 a = Wf2[F2_B4RS];
            #pragma unroll
            for (int m = 0; m < 2; m++)
                #pragma unroll
                for (int j = 0; j < 5; j++)
                    a = ffma2(Wf2[F2_W4RS + m * 5 + j], H3[idx(m, p - 4 + 2 * j)], a);
            float2 v = selu2(a);
            const size_t o0 = ((size_t)(2 * bp)     * 50 + sig) * NPOS + p;
            const size_t o1 = ((size_t)(2 * bp + 1) * 50 + sig) * NPOS + p;
            out[o0] = v.x;
            out[o1] = v.y;
        }
    }
}

// ---------------------------------------------------------------------------
// launch
// ---------------------------------------------------------------------------

static const int SMEM_PREP = (16 * CST) * (int)sizeof(float2) + 336 * 4 + 64 * (int)sizeof(float2);
static const int SMEM_SIG  = WSTRIDE * 4 + (10 * CST + 64) * (int)sizeof(float2);

extern "C" void kernel_launch(void* const* d_in, const int* in_sizes, int n_in,
                              void* d_out, int out_size) {
    const float* lat  = (const float*)d_in[0];
    const float* shw1 = (const float*)d_in[1];
    const float* shb1 = (const float*)d_in[2];
    const float* shw2 = (const float*)d_in[3];
    const float* shb2 = (const float*)d_in[4];
    const float* lng  = (const float*)d_in[5];
    const float* lnb  = (const float*)d_in[6];
    const float* sgw1 = (const float*)d_in[7];
    const float* sgb1 = (const float*)d_in[8];
    const float* sgw2 = (const float*)d_in[9];
    const float* sgb2 = (const float*)d_in[10];
    const float* sgw3 = (const float*)d_in[11];
    const float* sgb3 = (const float*)d_in[12];
    const float* sgw4 = (const float*)d_in[13];
    const float* sgb4 = (const float*)d_in[14];
    float* out = (float*)d_out;

    cudaFuncSetAttribute(prep_kernel, cudaFuncAttributeMaxDynamicSharedMemorySize, SMEM_PREP);
    cudaFuncSetAttribute(sig_kernel,  cudaFuncAttributeMaxDynamicSharedMemorySize, SMEM_SIG);

    wcomp_kernel<<<NSIG, 128>>>(sgw1, sgb1, sgw2, sgb2, sgw3, sgb3, sgw4, sgb4);
    prep_kernel<<<NBP, 512, SMEM_PREP>>>(lat, shw1, shb1, shw2, shb2, lng, lnb);
    sig_kernel<<<NCTA, 512, SMEM_SIG>>>(out);
}

// round 9
// speedup vs baseline: 1.3062x; 1.1293x over previous
#include <cuda_runtime.h>

// ---------------------------------------------------------------------------
// signalEncoding: B=256, S=512, SF=4, NSIG=50
// wcomp : compose per-signal weights once -> g_W (splatted float2 sections)
// prep  : x -> sharedCNN(sharedCNN(x)) + x -> LayerNorm -> g_D
// sig   : 128 thr, 4 contiguous positions/thread, swizzled SMEM,
//         ull-pure fma.rn.f32x2 (no float2 marshalling),
//         fused L12 (4->4 k11) uniform + edge overwrite, L3/L4 explicit.
// ---------------------------------------------------------------------------

#define NPOS 512
#define HALO 8
#define CST  528
#define NBP  128
#define NSIG 50
#define NITEM (NBP * NSIG)   // 6400
#define NCTA  592            // 4 CTAs/SM * 148 SMs
#define WSTRIDE 944          // floats per signal block (8B multiple)
#define WTOTAL  942

typedef unsigned long long ull;

// ull-index offsets (same as float2 indices)
#define F2_W12S  0    // [o*48 + c*12 + t], t<11 real
#define F2_BE12S 192
#define F2_W3RS  196  // [m*32 + c*8 + j], j<5 real
#define F2_B3RS  260
#define F2_W4RS  262  // [m*5 + j]
#define F2_B4RS  272
// raw float offsets
#define OFF_W2R  546
#define OFF_B2R  706
#define OFF_W1R  710
#define OFF_B1R  934

__device__ __forceinline__ int sidx(int c, int p) {
    int q = p + HALO;                    // q in [0, 527]
    return c * CST + (q ^ ((q >> 4) & 3));
}

__device__ __forceinline__ int refl(int q) {
    q = q < 0 ? -q : q;
    return q > 511 ? 1022 - q : q;
}

// ---- ull-pure packed math ----
__device__ __forceinline__ ull ffma2u(ull a, ull b, ull c) {
    ull d;
    asm("fma.rn.f32x2 %0, %1, %2, %3;" : "=l"(d) : "l"(a), "l"(b), "l"(c));
    return d;
}
__device__ __forceinline__ float ulo(ull v) { return __uint_as_float((unsigned)v); }
__device__ __forceinline__ float uhi(ull v) { return __uint_as_float((unsigned)(v >> 32)); }
__device__ __forceinline__ ull upack(float x, float y) {
    return (ull)__float_as_uint(x) | ((ull)__float_as_uint(y) << 32);
}

__device__ __forceinline__ float selu_f(float x) {
    const float SC = 1.0507009873554805f;
    const float SA = 1.7580993408473766f;
    return x > 0.f ? SC * x : SA * (__expf(x) - 1.0f);
}
__device__ __forceinline__ ull selu_u(ull v) {
    return upack(selu_f(ulo(v)), selu_f(uhi(v)));
}

// ---- float2 helpers for prep (validated; unchanged) ----
union F2U { float2 f; unsigned long long u; };
__device__ __forceinline__ float2 ffma2(float2 a, float2 b, float2 c) {
    F2U ua, ub, uc, ud;
    ua.f = a; ub.f = b; uc.f = c;
    asm("fma.rn.f32x2 %0, %1, %2, %3;" : "=l"(ud.u) : "l"(ua.u), "l"(ub.u), "l"(uc.u));
    return ud.f;
}
__device__ __forceinline__ float2 splat(float w) { return make_float2(w, w); }
__device__ __forceinline__ float2 add2(float2 a, float2 b) {
    return make_float2(a.x + b.x, a.y + b.y);
}
__device__ __forceinline__ float selu_s(float x) {
    const float SC = 1.0507009873554805f;
    const float SA = 1.7580993408473766f;
    return x > 0.f ? SC * x : SA * expm1f(x);
}
__device__ __forceinline__ float2 selu2(float2 v) {
    return make_float2(selu_s(v.x), selu_s(v.y));
}
__device__ __forceinline__ void fill_halo_sw(float2* buf, int C, int tid) {
    if (tid < C * 8) {
        int c = tid >> 3, k = tid & 7;
        if (k < 4) { int i = k + 1; buf[sidx(c, -i)]      = buf[sidx(c, i)]; }
        else       { int i = k - 3; buf[sidx(c, 511 + i)] = buf[sidx(c, 511 - i)]; }
    }
}

__device__ float2 g_D[NBP * 4 * NPOS];
__device__ __align__(16) float g_W[NSIG * WSTRIDE];

// ---------------------------------------------------------------------------
// wcomp (unchanged from R8, validated)
// ---------------------------------------------------------------------------

extern "C" __global__ void __launch_bounds__(128)
wcomp_kernel(const float* __restrict__ sw1, const float* __restrict__ sb1,
             const float* __restrict__ sw2, const float* __restrict__ sb2,
             const float* __restrict__ sw3, const float* __restrict__ sb3,
             const float* __restrict__ sw4, const float* __restrict__ sb4) {
    const int sig = blockIdx.x;
    float* w = g_W + sig * WSTRIDE;
    for (int i = threadIdx.x; i < WTOTAL; i += 128) {
        float v;
        if (i < 384) {
            int k = i >> 1, o = k / 48, r = k % 48, c = r / 12, t = r % 12;
            if (t == 11) v = 0.f;
            else {
                float s = 0.f;
                const float* w2p = sw2 + sig * 160 + o * 40;
                const float* w1p = sw1 + sig * 224;
                #pragma unroll
                for (int m = 0; m < 8; m++)
                    #pragma unroll
                    for (int j2 = 0; j2 < 5; j2++) {
                        int j1 = t - j2;
                        if (j1 >= 0 && j1 <= 6)
                            s += w2p[m * 5 + j2] * w1p[m * 28 + c * 7 + j1];
                    }
                v = s;
            }
        } else if (i < 392) {
            int o = (i - 384) >> 1;
            float s = sb2[sig * 4 + o];
            #pragma unroll
            for (int m = 0; m < 8; m++) {
                float sm_ = 0.f;
                #pragma unroll
                for (int j2 = 0; j2 < 5; j2++) sm_ += sw2[sig * 160 + o * 40 + m * 5 + j2];
                s += sm_ * sb1[sig * 8 + m];
            }
            v = s;
        } else if (i < 520) {
            int k = (i - 392) >> 1, m = k / 32, r = k % 32, c = r / 8, j = r % 8;
            v = (j < 5) ? sw3[sig * 40 + m * 20 + c * 5 + j] : 0.f;
        } else if (i < 524) {
            v = sb3[sig * 2 + ((i - 520) >> 1)];
        } else if (i < 544) {
            v = sw4[sig * 10 + ((i - 524) >> 1)];
        } else if (i < 546) {
            v = sb4[sig];
        } else if (i < 706) {
            v = sw2[sig * 160 + (i - OFF_W2R)];
        } else if (i < 710) {
            v = sb2[sig * 4 + (i - OFF_B2R)];
        } else if (i < 934) {
            v = sw1[sig * 224 + (i - OFF_W1R)];
        } else {
            v = sb1[sig * 8 + (i - OFF_B1R)];
        }
        w[i] = v;
    }
}

// ---------------------------------------------------------------------------
// prep (unchanged, validated)
// ---------------------------------------------------------------------------

__device__ __forceinline__ void shared_conv1(const float2* S, float2* Dst,
                                             const float* w1, const float* b1, int t) {
    #pragma unroll
    for (int o = 0; o < 8; o++) {
        float2 acc = splat(b1[o]);
        #pragma unroll
        for (int c = 0; c < 4; c++)
            #pragma unroll
            for (int j = 0; j < 5; j++) {
                float w = w1[o * 20 + c * 5 + j];
                acc = ffma2(splat(w), S[sidx(c, t - 2 + j)], acc);
            }
        Dst[sidx(o, t)] = selu2(acc);
    }
}

__device__ __forceinline__ void shared_conv2(const float2* S, const float* w2,
                                             const float* b2, int t, float2 out[4]) {
    #pragma unroll
    for (int o = 0; o < 4; o++) {
        float2 acc = splat(b2[o]);
        #pragma unroll
        for (int c = 0; c < 8; c++)
            #pragma unroll
            for (int j = 0; j < 5; j++) {
                float w = w2[o * 40 + c * 5 + j];
                acc = ffma2(splat(w), S[sidx(c, t - 4 + 2 * j)], acc);
            }
        out[o] = acc;
    }
}

extern "C" __global__ void __launch_bounds__(512)
prep_kernel(const float* __restrict__ lat,
            const float* __restrict__ sw1, const float* __restrict__ sb1,
            const float* __restrict__ sw2, const float* __restrict__ sb2,
            const float* __restrict__ lng, const float* __restrict__ lnb) {
    extern __shared__ unsigned char sm[];
    float2* X   = (float2*)sm;
    float2* A   = X + 4 * CST;
    float2* Bu  = A + 8 * CST;
    float*  W   = (float*)(Bu + 4 * CST);
    float2* RED = (float2*)(W + 336);

    const int t  = threadIdx.x;
    const int bp = blockIdx.x;
    const int lane = t & 31, wid = t >> 5;

    if (t < 332) {
        float v;
        if      (t < 160) v = sw1[t];
        else if (t < 168) v = sb1[t - 160];
        else if (t < 328) v = sw2[t - 168];
        else              v = sb2[t - 328];
        W[t] = v;
    }
    const float* w1 = W, * b1 = W + 160, * w2 = W + 168, * b2 = W + 328;

    float4 v0 = reinterpret_cast<const float4*>(lat + (size_t)(2 * bp)     * 2048)[t];
    float4 v1 = reinterpret_cast<const float4*>(lat + (size_t)(2 * bp + 1) * 2048)[t];
    X[sidx(0, t)] = make_float2(v0.x, v1.x);
    X[sidx(1, t)] = make_float2(v0.y, v1.y);
    X[sidx(2, t)] = make_float2(v0.z, v1.z);
    X[sidx(3, t)] = make_float2(v0.w, v1.w);
    __syncthreads();
    fill_halo_sw(X, 4, t);
    __syncthreads();

    shared_conv1(X, A, w1, b1, t);
    __syncthreads(); fill_halo_sw(A, 8, t); __syncthreads();
    {
        float2 tmp[4];
        shared_conv2(A, w2, b2, t, tmp);
        __syncthreads();
        #pragma unroll
        for (int c = 0; c < 4; c++) Bu[sidx(c, t)] = tmp[c];
    }
    __syncthreads(); fill_halo_sw(Bu, 4, t); __syncthreads();

    shared_conv1(Bu, A, w1, b1, t);
    __syncthreads(); fill_halo_sw(A, 8, t); __syncthreads();
    float2 dv[4];
    {
        float2 cc[4];
        shared_conv2(A, w2, b2, t, cc);
        #pragma unroll
        for (int c = 0; c < 4; c++) dv[c] = add2(cc[c], X[sidx(c, t)]);
    }

    float2 mean[4], var[4];
    {
        float2 sv[4];
        #pragma unroll
        for (int c = 0; c < 4; c++) sv[c] = dv[c];
        #pragma unroll
        for (int c = 0; c < 4; c++)
            for (int off = 16; off; off >>= 1) {
                sv[c].x += __shfl_xor_sync(0xffffffffu, sv[c].x, off);
                sv[c].y += __shfl_xor_sync(0xffffffffu, sv[c].y, off);
            }
        if (lane == 0)
            #pragma unroll
            for (int c = 0; c < 4; c++) RED[c * 16 + wid] = sv[c];
        __syncthreads();
        if (t < 32) {
            #pragma unroll
            for (int c = 0; c < 4; c++) {
                float2 v = (lane < 16) ? RED[c * 16 + lane] : make_float2(0.f, 0.f);
                for (int off = 8; off; off >>= 1) {
                    v.x += __shfl_xor_sync(0xffffffffu, v.x, off);
                    v.y += __shfl_xor_sync(0xffffffffu, v.y, off);
                }
                if (lane == 0) RED[c * 16] = v;
            }
        }
        __syncthreads();
        const float inv = 1.0f / 512.0f;
        #pragma unroll
        for (int c = 0; c < 4; c++) {
            float2 s = RED[c * 16];
            mean[c] = make_float2(s.x * inv, s.y * inv);
        }
        __syncthreads();
    }
    {
        float2 sv[4];
        #pragma unroll
        for (int c = 0; c < 4; c++) {
            float dx = dv[c].x - mean[c].x, dy = dv[c].y - mean[c].y;
            sv[c] = make_float2(dx * dx, dy * dy);
        }
        #pragma unroll
        for (int c = 0; c < 4; c++)
            for (int off = 16; off; off >>= 1) {
                sv[c].x += __shfl_xor_sync(0xffffffffu, sv[c].x, off);
                sv[c].y += __shfl_xor_sync(0xffffffffu, sv[c].y, off);
            }
        if (lane == 0)
            #pragma unroll
            for (int c = 0; c < 4; c++) RED[c * 16 + wid] = sv[c];
        __syncthreads();
        if (t < 32) {
            #pragma unroll
            for (int c = 0; c < 4; c++) {
                float2 v = (lane < 16) ? RED[c * 16 + lane] : make_float2(0.f, 0.f);
                for (int off = 8; off; off >>= 1) {
                    v.x += __shfl_xor_sync(0xffffffffu, v.x, off);
                    v.y += __shfl_xor_sync(0xffffffffu, v.y, off);
                }
                if (lane == 0) RED[c * 16] = v;
            }
        }
        __syncthreads();
        const float inv = 1.0f / 512.0f;
        #pragma unroll
        for (int c = 0; c < 4; c++) {
            float2 s = RED[c * 16];
            var[c] = make_float2(s.x * inv, s.y * inv);
        }
    }

    const float EPS = 1e-10f;
    float g = lng[t], bb = lnb[t];
    #pragma unroll
    for (int c = 0; c < 4; c++) {
        float rx = 1.0f / sqrtf(var[c].x + EPS);
        float ry = 1.0f / sqrtf(var[c].y + EPS);
        float2 dn;
        dn.x = (dv[c].x - mean[c].x) * rx * g + bb;
        dn.y = (dv[c].y - mean[c].y) * ry * g + bb;
        g_D[(size_t)(bp * 4 + c) * NPOS + t] = dn;
    }
}

// ---------------------------------------------------------------------------
// sig: 128 threads, 4 contiguous positions/thread, ull-pure math.
// ---------------------------------------------------------------------------

extern "C" __global__ void __launch_bounds__(128, 4)
sig_kernel(float* __restrict__ out) {
    extern __shared__ ull smu[];
    ull* Wsm = smu;                 // 472 ull
    ull* D   = smu + 472;           // 4*CST
    ull* H2  = D + 4 * CST;         // 4*CST
    ull* H3  = H2 + 4 * CST;        // 2*CST
    ull* He  = H3 + 2 * CST;        // 64
    const float* Wf = (const float*)Wsm;

    const int tid  = threadIdx.x;
    const int base = tid * 4;
    const bool is_edge_lo = (tid == 0), is_edge_hi = (tid == 127);
    const bool near_edge  = (tid < 2) || (tid >= 126);

    const int kcta  = blockIdx.x;
    const int start = (int)(((long long)kcta * NITEM) / NCTA);
    const int end   = (int)(((long long)(kcta + 1) * NITEM) / NCTA);

    int cur_bp = -1;

    for (int it = start; it < end; ++it) {
        const int bp  = it / NSIG;
        const int sig = it - bp * NSIG;

        __syncthreads();   // prior item's smem reads complete

        if (bp != cur_bp) {
            const ull* gd = (const ull*)(g_D + (size_t)bp * 4 * NPOS);
            for (int i = tid; i < 4 * NPOS; i += 128) {
                int c = i >> 9, pp = i & 511;
                ull v = gd[i];
                D[sidx(c, pp)] = v;
                if (pp >= 1 && pp <= 5)     D[sidx(c, -pp)]       = v;
                if (pp >= 506 && pp <= 510) D[sidx(c, 1022 - pp)] = v;
            }
            cur_bp = bp;
            __syncthreads();
        }

        const float* gw  = g_W + sig * WSTRIDE;
        const ull*   gwu = (const ull*)gw;

        // stage: tids >=64 copy weights (471 ull); tids <64 compute H1 edges
        if (tid >= 64) {
            for (int i = tid - 64; i < 471; i += 64) Wsm[i] = gwu[i];
        } else {
            int m = tid >> 3, kk = tid & 7;
            int q = kk < 4 ? kk : 508 + (kk - 4);
            float ax = gw[OFF_B1R + m], ay = ax;
            const float* w1p = gw + OFF_W1R + m * 28;
            #pragma unroll
            for (int c = 0; c < 4; c++)
                #pragma unroll
                for (int j1 = 0; j1 < 7; j1++) {
                    float w = w1p[c * 7 + j1];
                    ull dv = D[sidx(c, q - 3 + j1)];
                    ax = fmaf(w, ulo(dv), ax);
                    ay = fmaf(w, uhi(dv), ay);
                }
            He[tid] = upack(ax, ay);
        }
        __syncthreads();

        // ---- L12: composed 4->4 k11, uniform; edges overwritten after ----
        {
            ull acc[4][4];
            #pragma unroll
            for (int o = 0; o < 4; o++) {
                ull b = Wsm[F2_BE12S + o];
                #pragma unroll
                for (int r = 0; r < 4; r++) acc[o][r] = b;
            }
            #pragma unroll
            for (int c = 0; c < 4; c++) {
                ull din[14];
                #pragma unroll
                for (int t = 0; t < 14; t++) din[t] = D[sidx(c, base - 5 + t)];
                #pragma unroll
                for (int o = 0; o < 4; o++) {
                    const ull* wp = Wsm + F2_W12S + o * 48 + c * 12;
                    #pragma unroll
                    for (int t = 0; t < 11; t++) {
                        ull w = wp[t];
                        #pragma unroll
                        for (int r = 0; r < 4; r++)
                            acc[o][r] = ffma2u(w, din[t + r], acc[o][r]);
                    }
                }
            }
            #pragma unroll
            for (int o = 0; o < 4; o++)
                #pragma unroll
                for (int r = 0; r < 4; r++)
                    H2[sidx(o, base + r)] = selu_u(acc[o][r]);

            // exact edge overwrite: p in {0,1} (tid 0) / {510,511} (tid 127)
            if (is_edge_lo || is_edge_hi) {
                #pragma unroll
                for (int e = 0; e < 2; e++) {
                    int p = is_edge_lo ? e : 510 + e;
                    #pragma unroll
                    for (int o = 0; o < 4; o++) {
                        float ax = Wf[OFF_B2R + o], ay = ax;
                        #pragma unroll
                        for (int m = 0; m < 8; m++)
                            #pragma unroll
                            for (int j2 = 0; j2 < 5; j2++) {
                                int q = refl(p - 2 + j2);
                                int k = q < 8 ? q : q - 504;
                                float w = Wf[OFF_W2R + o * 40 + m * 5 + j2];
                                ull he = He[m * 8 + k];
                                ax = fmaf(w, ulo(he), ax);
                                ay = fmaf(w, uhi(he), ay);
                            }
                        H2[sidx(o, p)] = upack(selu_f(ax), selu_f(ay));
                    }
                }
            }
            // halo mirrors (own positions only; after any overwrite)
            if (near_edge) {
                #pragma unroll
                for (int r = 0; r < 4; r++) {
                    int p = base + r;
                    if (p >= 1 && p <= 4)
                        #pragma unroll
                        for (int o = 0; o < 4; o++)
                            H2[sidx(o, -p)] = H2[sidx(o, p)];
                    if (p >= 507 && p <= 510)
                        #pragma unroll
                        for (int o = 0; o < 4; o++)
                            H2[sidx(o, 1022 - p)] = H2[sidx(o, p)];
                }
            }
        }
        __syncthreads();

        // ---- L3: 4->2 k5 (linear) -> H3, uniform ----
        {
            ull a3[2][4];
            #pragma unroll
            for (int m = 0; m < 2; m++) {
                ull b = Wsm[F2_B3RS + m];
                #pragma unroll
                for (int r = 0; r < 4; r++) a3[m][r] = b;
            }
            #pragma unroll
            for (int c = 0; c < 4; c++) {
                ull h[8];
                #pragma unroll
                for (int k = 0; k < 8; k++) h[k] = H2[sidx(c, base - 2 + k)];
                #pragma unroll
                for (int m = 0; m < 2; m++) {
                    const ull* wp = Wsm + F2_W3RS + m * 32 + c * 8;
                    #pragma unroll
                    for (int j = 0; j < 5; j++) {
                        ull w = wp[j];
                        #pragma unroll
                        for (int r = 0; r < 4; r++)
                            a3[m][r] = ffma2u(w, h[j + r], a3[m][r]);
                    }
                }
            }
            #pragma unroll
            for (int m = 0; m < 2; m++)
                #pragma unroll
                for (int r = 0; r < 4; r++)
                    H3[sidx(m, base + r)] = a3[m][r];
            if (near_edge) {
                #pragma unroll
                for (int r = 0; r < 4; r++) {
                    int p = base + r;
                    if (p >= 1 && p <= 4) {
                        H3[sidx(0, -p)] = H3[sidx(0, p)];
                        H3[sidx(1, -p)] = H3[sidx(1, p)];
                    }
                    if (p >= 507 && p <= 510) {
                        H3[sidx(0, 1022 - p)] = H3[sidx(0, p)];
                        H3[sidx(1, 1022 - p)] = H3[sidx(1, p)];
                    }
                }
            }
        }
        __syncthreads();

        // ---- L4: 2->1 k5 d2 + SELU -> out ----
        {
            ull a4[4];
            ull b = Wsm[F2_B4RS];
            #pragma unroll
            for (int r = 0; r < 4; r++) a4[r] = b;
            #pragma unroll
            for (int m = 0; m < 2; m++) {
                ull h[12];
                #pragma unroll
                for (int k = 0; k < 12; k++) h[k] = H3[sidx(m, base - 4 + k)];
                const ull* wp = Wsm + F2_W4RS + m * 5;
                #pragma unroll
                for (int j = 0; j < 5; j++) {
                    ull w = wp[j];
                    #pragma unroll
                    for (int r = 0; r < 4; r++)
                        a4[r] = ffma2u(w, h[2 * j + r], a4[r]);
                }
            }
            float x0, x1, x2, x3, y0, y1, y2, y3;
            {
                ull v0 = selu_u(a4[0]), v1 = selu_u(a4[1]);
                ull v2 = selu_u(a4[2]), v3 = selu_u(a4[3]);
                x0 = ulo(v0); y0 = uhi(v0);
                x1 = ulo(v1); y1 = uhi(v1);
                x2 = ulo(v2); y2 = uhi(v2);
                x3 = ulo(v3); y3 = uhi(v3);
            }
            const size_t o0 = ((size_t)(2 * bp)     * 50 + sig) * NPOS + base;
            const size_t o1 = ((size_t)(2 * bp + 1) * 50 + sig) * NPOS + base;
            *reinterpret_cast<float4*>(out + o0) = make_float4(x0, x1, x2, x3);
            *reinterpret_cast<float4*>(out + o1) = make_float4(y0, y1, y2, y3);
        }
    }
}

// ---------------------------------------------------------------------------
// launch
// ---------------------------------------------------------------------------

static const int SMEM_PREP = (16 * CST) * (int)sizeof(float2) + 336 * 4 + 64 * (int)sizeof(float2);
static const int SMEM_SIG  = (472 + 10 * CST + 64) * (int)sizeof(ull);

extern "C" void kernel_launch(void* const* d_in, const int* in_sizes, int n_in,
                              void* d_out, int out_size) {
    const float* lat  = (const float*)d_in[0];
    const float* shw1 = (const float*)d_in[1];
    const float* shb1 = (const float*)d_in[2];
    const float* shw2 = (const float*)d_in[3];
    const float* shb2 = (const float*)d_in[4];
    const float* lng  = (const float*)d_in[5];
    const float* lnb  = (const float*)d_in[6];
    const float* sgw1 = (const float*)d_in[7];
    const float* sgb1 = (const float*)d_in[8];
    const float* sgw2 = (const float*)d_in[9];
    const float* sgb2 = (const float*)d_in[10];
    const float* sgw3 = (const float*)d_in[11];
    const float* sgb3 = (const float*)d_in[12];
    const float* sgw4 = (const float*)d_in[13];
    const float* sgb4 = (const float*)d_in[14];
    float* out = (float*)d_out;

    cudaFuncSetAttribute(prep_kernel, cudaFuncAttributeMaxDynamicSharedMemorySize, SMEM_PREP);
    cudaFuncSetAttribute(sig_kernel,  cudaFuncAttributeMaxDynamicSharedMemorySize, SMEM_SIG);

    wcomp_kernel<<<NSIG, 128>>>(sgw1, sgb1, sgw2, sgb2, sgw3, sgb3, sgw4, sgb4);
    prep_kernel<<<NBP, 512, SMEM_PREP>>>(lat, shw1, shb1, shw2, shb2, lng, lnb);
    sig_kernel<<<NCTA, 128, SMEM_SIG>>>(out);
}